// round 5
// baseline (speedup 1.0000x reference)
#include <cuda_runtime.h>
#include <cstdint>

// Problem constants
#define T_STEPS  4
#define P_DIM    63
#define D_DIM    128
#define BN_ROWS  65536              // B*N = 64*1024
#define M_TOTAL  262144             // T*B*N
#define N_TILES  4096               // M_TOTAL / 64

// Packed fp32x2 helpers (sm_103a). Per-lane IEEE fp32 FMA -> bit-identical to
// scalar fmaf done in the same order.
#define FMA2(d, a, b) \
    asm("fma.rn.f32x2 %0, %1, %2, %0;" : "+l"(d) : "l"(a), "l"(b))
#define PACK2(out, lo, hi) \
    asm("mov.b64 %0, {%1, %2};" : "=l"(out) : "f"(lo), "f"(hi))
#define UNPACK2(lo, hi, in) \
    asm("mov.b64 {%0, %1}, %2;" : "=f"(lo), "=f"(hi) : "l"(in))

// Scratch (no allocations allowed -> __device__ globals)
__device__ double g_C[64 * 64];     // S = sum_m x_m x_m^T  (cols 63 padded with zeros)
__device__ double g_colsum[64];     // per-feature column sums of x
__device__ float4 g_prm[D_DIM];     // per-channel (mean, rsqrt(var+eps), gamma, beta)

// ---------------------------------------------------------------------------
// Kernel 0: zero the stat accumulators (must run every launch: graph replays)
// ---------------------------------------------------------------------------
__global__ void zero_stats_kernel() {
    int i = blockIdx.x * blockDim.x + threadIdx.x;
    if (i < 64 * 64) g_C[i] = 0.0;
    if (i < 64)      g_colsum[i] = 0.0;
}

// ---------------------------------------------------------------------------
// Kernel 1: stats pass.  S += X^T X  and colsum += X^T 1 over all M rows.
// 4x4 per-thread tile of S, inner products done as 8 FFMA2 per staged row.
// Per-element accumulation order identical to the scalar version.
// ---------------------------------------------------------------------------
__global__ __launch_bounds__(256) void stats_kernel(const float* __restrict__ x) {
    __shared__ __align__(16) float xs[64][64];
    const int tid = threadIdx.x;
    const int ti = tid >> 4;
    const int tj = tid & 15;
    const int col = tid & 63;
    const int rg  = tid >> 6;

    uint64_t c2[4][2];
    #pragma unroll
    for (int i = 0; i < 4; i++) { c2[i][0] = 0ull; c2[i][1] = 0ull; }
    float csum = 0.f;

    for (int tile = blockIdx.x; tile < N_TILES; tile += gridDim.x) {
        __syncthreads();
        const float* xb = x + (size_t)tile * (64 * 63);
        for (int i2 = tid; i2 < 64 * 64; i2 += 256) {
            int r = i2 >> 6, cc = i2 & 63;
            xs[r][cc] = (cc < 63) ? xb[r * 63 + cc] : 0.f;
        }
        __syncthreads();

        #pragma unroll 4
        for (int r = rg; r < 64; r += 4) csum += xs[r][col];

        #pragma unroll 4
        for (int r = 0; r < 64; r++) {
            float4 a = *(const float4*)&xs[r][4 * ti];
            const uint64_t* pb = (const uint64_t*)&xs[r][4 * tj];
            uint64_t b01 = pb[0], b23 = pb[1];
            uint64_t aa;
            PACK2(aa, a.x, a.x);
            FMA2(c2[0][0], aa, b01); FMA2(c2[0][1], aa, b23);
            PACK2(aa, a.y, a.y);
            FMA2(c2[1][0], aa, b01); FMA2(c2[1][1], aa, b23);
            PACK2(aa, a.z, a.z);
            FMA2(c2[2][0], aa, b01); FMA2(c2[2][1], aa, b23);
            PACK2(aa, a.w, a.w);
            FMA2(c2[3][0], aa, b01); FMA2(c2[3][1], aa, b23);
        }
    }

    __syncthreads();
    xs[rg][col] = csum;
    __syncthreads();
    if (tid < 64) {
        float s = xs[0][tid] + xs[1][tid] + xs[2][tid] + xs[3][tid];
        atomicAdd(&g_colsum[tid], (double)s);
    }

    const int rbase = 4 * ti, cbase = 4 * tj;
    #pragma unroll
    for (int i = 0; i < 4; i++) {
        float v0, v1, v2, v3;
        UNPACK2(v0, v1, c2[i][0]);
        UNPACK2(v2, v3, c2[i][1]);
        atomicAdd(&g_C[(rbase + i) * 64 + cbase + 0], (double)v0);
        atomicAdd(&g_C[(rbase + i) * 64 + cbase + 1], (double)v1);
        atomicAdd(&g_C[(rbase + i) * 64 + cbase + 2], (double)v2);
        atomicAdd(&g_C[(rbase + i) * 64 + cbase + 3], (double)v3);
    }
}

// ---------------------------------------------------------------------------
// Kernel 2: finalize per-channel BN params from S and colsum. (unchanged)
// ---------------------------------------------------------------------------
__global__ void finalize_kernel(const float* __restrict__ W,
                                const float* __restrict__ gamma,
                                const float* __restrict__ beta) {
    __shared__ double s1[64];
    __shared__ double s2[64];
    const int d = blockIdx.x;
    const int p = threadIdx.x;

    double t1 = 0.0, t2 = 0.0;
    if (p < P_DIM) {
        double wp = (double)W[d * P_DIM + p];
        t1 = wp * g_colsum[p];
        double acc = 0.0;
        for (int q = 0; q < P_DIM; q++)
            acc += (double)W[d * P_DIM + q] * g_C[p * 64 + q];
        t2 = wp * acc;
    }
    s1[p] = t1; s2[p] = t2;
    __syncthreads();
    for (int s = 32; s > 0; s >>= 1) {
        if (p < s) { s1[p] += s1[p + s]; s2[p] += s2[p + s]; }
        __syncthreads();
    }
    if (p == 0) {
        const double inv = 1.0 / (double)M_TOTAL;
        double mean = s1[0] * inv;
        double var  = s2[0] * inv - mean * mean;
        float rsq = (float)(1.0 / sqrt(var + 1e-5));
        g_prm[d] = make_float4((float)mean, rsq, gamma[d], beta[d]);
    }
}

// ---------------------------------------------------------------------------
// Kernel 3: fused GEMM + BatchNorm + 4-step LIF.
// 256 threads/block, tile 64 rows x 128 channels, 4-row x 8-channel register
// tile per thread with f32x2 packed accumulation (lanes = channel pairs).
// v (membrane) lives in fp32 registers across t. Epilogue numerics identical
// to the rel_err=0 kernel.
// ---------------------------------------------------------------------------
__global__ __launch_bounds__(256, 2) void lif_main_kernel(
    const float* __restrict__ x,
    const float* __restrict__ W,
    float* __restrict__ out) {
    __shared__ __align__(16) float xs[64][65];     // 16.6 KB
    __shared__ __align__(16) float Wa[P_DIM][64];  // 15.75 KB  (ch 8g..8g+3)
    __shared__ __align__(16) float Wb[P_DIM][64];  // 15.75 KB  (ch 8g+4..8g+7)

    const int tid = threadIdx.x;
    const int tR = tid >> 4;     // 0..15 -> rows 4*tR .. 4*tR+3
    const int tC = tid & 15;     // 0..15 -> channels 8*tC .. 8*tC+7
    const int row0 = blockIdx.x * 64;

    // stage W: Wa[k][4g+j] = W[(8g+j)*63+k], Wb[k][4g+j] = W[(8g+4+j)*63+k]
    for (int i = tid; i < P_DIM * 64; i += 256) {
        int k = i >> 6, c = i & 63;
        int g = c >> 2, j = c & 3;
        Wa[k][c] = W[(8 * g + j)     * P_DIM + k];
        Wb[k][c] = W[(8 * g + 4 + j) * P_DIM + k];
    }

    float v[4][8];
    #pragma unroll
    for (int i = 0; i < 4; i++)
        #pragma unroll
        for (int j = 0; j < 8; j++) v[i][j] = 0.f;

    for (int t = 0; t < T_STEPS; t++) {
        __syncthreads();  // also covers the W staging before first use
        const float* xb = x + ((size_t)t * BN_ROWS + row0) * P_DIM;
        for (int i2 = tid; i2 < 64 * P_DIM; i2 += 256) {
            int r = i2 / P_DIM, cc = i2 - r * P_DIM;
            xs[r][cc] = xb[i2];
        }
        __syncthreads();

        uint64_t acc2[4][4];        // [row][channel-pair]
        #pragma unroll
        for (int i = 0; i < 4; i++)
            #pragma unroll
            for (int j = 0; j < 4; j++) acc2[i][j] = 0ull;

        #pragma unroll 1
        for (int k = 0; k < P_DIM; k++) {
            const uint64_t* pwa = (const uint64_t*)&Wa[k][4 * tC];
            uint64_t w0 = pwa[0], w1 = pwa[1];
            const uint64_t* pwb = (const uint64_t*)&Wb[k][4 * tC];
            uint64_t w2 = pwb[0], w3 = pwb[1];
            #pragma unroll
            for (int i = 0; i < 4; i++) {
                float a = xs[4 * tR + i][k];
                uint64_t aa;
                PACK2(aa, a, a);
                FMA2(acc2[i][0], aa, w0);
                FMA2(acc2[i][1], aa, w1);
                FMA2(acc2[i][2], aa, w2);
                FMA2(acc2[i][3], aa, w3);
            }
        }

        // BN + LIF epilogue; same arithmetic order as the rel_err=0 kernel.
        #pragma unroll
        for (int i = 0; i < 4; i++) {
            float acc[8];
            UNPACK2(acc[0], acc[1], acc2[i][0]);
            UNPACK2(acc[2], acc[3], acc2[i][1]);
            UNPACK2(acc[4], acc[5], acc2[i][2]);
            UNPACK2(acc[6], acc[7], acc2[i][3]);
            float sv[8];
            #pragma unroll
            for (int j = 0; j < 8; j++) {
                float4 prm = g_prm[8 * tC + j];     // (mean, rsq, gamma, beta)
                float h = (acc[j] - prm.x) * prm.y;
                h = h * prm.z + prm.w;
                float vv = v[i][j] + (h - v[i][j]) * 0.5f;        // v + (x-v)/tau
                float s = ((vv - 1.0f) >= 0.0f) ? 1.0f : 0.0f;    // H(v'-1)
                v[i][j] = vv * (1.0f - s);                        // hard reset
                sv[j] = s;
            }
            size_t o = ((size_t)t * BN_ROWS + row0 + 4 * tR + i) * D_DIM + 8 * tC;
            *(float4*)&out[o]     = make_float4(sv[0], sv[1], sv[2], sv[3]);
            *(float4*)&out[o + 4] = make_float4(sv[4], sv[5], sv[6], sv[7]);
        }
    }
}

// ---------------------------------------------------------------------------
extern "C" void kernel_launch(void* const* d_in, const int* in_sizes, int n_in,
                              void* d_out, int out_size) {
    const float* x     = (const float*)d_in[0];   // [4,64,1024,63]
    const float* W     = (const float*)d_in[1];   // [128,63]
    const float* gamma = (const float*)d_in[2];   // [128]
    const float* beta  = (const float*)d_in[3];   // [128]
    float* out = (float*)d_out;                   // [4,64,1024,128]

    zero_stats_kernel<<<16, 256>>>();
    stats_kernel<<<1024, 256>>>(x);
    finalize_kernel<<<D_DIM, 64>>>(W, gamma, beta);
    lif_main_kernel<<<BN_ROWS / 64, 256>>>(x, W, out);
}

// round 6
// speedup vs baseline: 1.2559x; 1.2559x over previous
#include <cuda_runtime.h>
#include <cstdint>

// Problem constants
#define T_STEPS  4
#define P_DIM    63
#define D_DIM    128
#define BN_ROWS  65536              // B*N = 64*1024
#define M_TOTAL  262144             // T*B*N
#define N_TILES  4096               // M_TOTAL / 64

// Scratch (no allocations allowed -> __device__ globals)
__device__ double g_C[64 * 64];     // S = sum_m x_m x_m^T  (cols 63 padded with zeros)
__device__ double g_colsum[64];     // per-feature column sums of x
__device__ float4 g_prm[D_DIM];     // per-channel (mean, rsqrt(var+eps), gamma, beta)
__device__ float  g_v[BN_ROWS * D_DIM];  // LIF membrane potential between t-steps (32MB)

// ---------------------------------------------------------------------------
// Kernel 0: zero the stat accumulators (must run every launch: graph replays)
// ---------------------------------------------------------------------------
__global__ void zero_stats_kernel() {
    int i = blockIdx.x * blockDim.x + threadIdx.x;
    if (i < 64 * 64) g_C[i] = 0.0;
    if (i < 64)      g_colsum[i] = 0.0;
}

// ---------------------------------------------------------------------------
// Kernel 1: stats pass.  S += X^T X  and colsum += X^T 1 over all M rows.
// (scalar round-3 version, known good)
// ---------------------------------------------------------------------------
__global__ __launch_bounds__(256) void stats_kernel(const float* __restrict__ x) {
    __shared__ __align__(16) float xs[64][64];
    const int tid = threadIdx.x;
    const int ti = tid >> 4;
    const int tj = tid & 15;
    const int col = tid & 63;
    const int rg  = tid >> 6;

    float c00=0.f,c01=0.f,c02=0.f,c03=0.f;
    float c10=0.f,c11=0.f,c12=0.f,c13=0.f;
    float c20=0.f,c21=0.f,c22=0.f,c23=0.f;
    float c30=0.f,c31=0.f,c32=0.f,c33=0.f;
    float csum = 0.f;

    for (int tile = blockIdx.x; tile < N_TILES; tile += gridDim.x) {
        __syncthreads();
        const float* xb = x + (size_t)tile * (64 * 63);
        for (int i2 = tid; i2 < 64 * 64; i2 += 256) {
            int r = i2 >> 6, cc = i2 & 63;
            xs[r][cc] = (cc < 63) ? xb[r * 63 + cc] : 0.f;
        }
        __syncthreads();

        #pragma unroll 4
        for (int r = rg; r < 64; r += 4) csum += xs[r][col];

        #pragma unroll 4
        for (int r = 0; r < 64; r++) {
            float4 a = *(const float4*)&xs[r][4 * ti];
            float4 b = *(const float4*)&xs[r][4 * tj];
            c00 = fmaf(a.x, b.x, c00); c01 = fmaf(a.x, b.y, c01);
            c02 = fmaf(a.x, b.z, c02); c03 = fmaf(a.x, b.w, c03);
            c10 = fmaf(a.y, b.x, c10); c11 = fmaf(a.y, b.y, c11);
            c12 = fmaf(a.y, b.z, c12); c13 = fmaf(a.y, b.w, c13);
            c20 = fmaf(a.z, b.x, c20); c21 = fmaf(a.z, b.y, c21);
            c22 = fmaf(a.z, b.z, c22); c23 = fmaf(a.z, b.w, c23);
            c30 = fmaf(a.w, b.x, c30); c31 = fmaf(a.w, b.y, c31);
            c32 = fmaf(a.w, b.z, c32); c33 = fmaf(a.w, b.w, c33);
        }
    }

    __syncthreads();
    xs[rg][col] = csum;
    __syncthreads();
    if (tid < 64) {
        float s = xs[0][tid] + xs[1][tid] + xs[2][tid] + xs[3][tid];
        atomicAdd(&g_colsum[tid], (double)s);
    }

    const int rbase = 4 * ti, cbase = 4 * tj;
    atomicAdd(&g_C[(rbase+0)*64 + cbase+0], (double)c00);
    atomicAdd(&g_C[(rbase+0)*64 + cbase+1], (double)c01);
    atomicAdd(&g_C[(rbase+0)*64 + cbase+2], (double)c02);
    atomicAdd(&g_C[(rbase+0)*64 + cbase+3], (double)c03);
    atomicAdd(&g_C[(rbase+1)*64 + cbase+0], (double)c10);
    atomicAdd(&g_C[(rbase+1)*64 + cbase+1], (double)c11);
    atomicAdd(&g_C[(rbase+1)*64 + cbase+2], (double)c12);
    atomicAdd(&g_C[(rbase+1)*64 + cbase+3], (double)c13);
    atomicAdd(&g_C[(rbase+2)*64 + cbase+0], (double)c20);
    atomicAdd(&g_C[(rbase+2)*64 + cbase+1], (double)c21);
    atomicAdd(&g_C[(rbase+2)*64 + cbase+2], (double)c22);
    atomicAdd(&g_C[(rbase+2)*64 + cbase+3], (double)c23);
    atomicAdd(&g_C[(rbase+3)*64 + cbase+0], (double)c30);
    atomicAdd(&g_C[(rbase+3)*64 + cbase+1], (double)c31);
    atomicAdd(&g_C[(rbase+3)*64 + cbase+2], (double)c32);
    atomicAdd(&g_C[(rbase+3)*64 + cbase+3], (double)c33);
}

// ---------------------------------------------------------------------------
// Kernel 2: finalize per-channel BN params from S and colsum. (unchanged)
// ---------------------------------------------------------------------------
__global__ void finalize_kernel(const float* __restrict__ W,
                                const float* __restrict__ gamma,
                                const float* __restrict__ beta) {
    __shared__ double s1[64];
    __shared__ double s2[64];
    const int d = blockIdx.x;
    const int p = threadIdx.x;

    double t1 = 0.0, t2 = 0.0;
    if (p < P_DIM) {
        double wp = (double)W[d * P_DIM + p];
        t1 = wp * g_colsum[p];
        double acc = 0.0;
        for (int q = 0; q < P_DIM; q++)
            acc += (double)W[d * P_DIM + q] * g_C[p * 64 + q];
        t2 = wp * acc;
    }
    s1[p] = t1; s2[p] = t2;
    __syncthreads();
    for (int s = 32; s > 0; s >>= 1) {
        if (p < s) { s1[p] += s1[p + s]; s2[p] += s2[p + s]; }
        __syncthreads();
    }
    if (p == 0) {
        const double inv = 1.0 / (double)M_TOTAL;
        double mean = s1[0] * inv;
        double var  = s2[0] * inv - mean * mean;
        float rsq = (float)(1.0 / sqrt(var + 1e-5));
        g_prm[d] = make_float4((float)mean, rsq, gamma[d], beta[d]);
    }
}

// ---------------------------------------------------------------------------
// Kernel 3: fused GEMM + BatchNorm + 4-step LIF.
// 128 threads/block, 64 rows x 128 channels, 8x8 scalar register tile.
// v (membrane) lives in GLOBAL scratch between t-steps: it is only touched in
// the epilogue, dropping k-loop register pressure from 184 to ~110 so 4 CTAs
// (16 warps) fit per SM. fp32 round-trip through memory is bit-exact.
// ---------------------------------------------------------------------------
__global__ __launch_bounds__(128, 4) void lif_main_kernel(
    const float* __restrict__ x,
    const float* __restrict__ W,
    float* __restrict__ out) {
    __shared__ __align__(16) float xs[64][65];     // 16.6 KB
    __shared__ __align__(16) float Wa[P_DIM][64];  // 15.75 KB  (ch 8g..8g+3)
    __shared__ __align__(16) float Wb[P_DIM][64];  // 15.75 KB  (ch 8g+4..8g+7)

    const int tid = threadIdx.x;
    const int tR = tid >> 4;     // 0..7  -> rows 8*tR .. 8*tR+7
    const int tC = tid & 15;     // 0..15 -> channels 8*tC .. 8*tC+7
    const int row0 = blockIdx.x * 64;

    // stage W: Wa[k][4g+j] = W[(8g+j)*63+k], Wb[k][4g+j] = W[(8g+4+j)*63+k]
    for (int i = tid; i < P_DIM * 64; i += 128) {
        int k = i >> 6, c = i & 63;
        int g = c >> 2, j = c & 3;
        Wa[k][c] = W[(8 * g + j)     * P_DIM + k];
        Wb[k][c] = W[(8 * g + 4 + j) * P_DIM + k];
    }

    for (int t = 0; t < T_STEPS; t++) {
        __syncthreads();  // also covers the W staging before first use
        const float* xb = x + ((size_t)t * BN_ROWS + row0) * P_DIM;
        for (int i2 = tid; i2 < 64 * P_DIM; i2 += 128) {
            int r = i2 / P_DIM, cc = i2 - r * P_DIM;
            xs[r][cc] = xb[i2];
        }
        __syncthreads();

        float acc[8][8];
        #pragma unroll
        for (int i = 0; i < 8; i++)
            #pragma unroll
            for (int j = 0; j < 8; j++) acc[i][j] = 0.f;

        #pragma unroll 1
        for (int k = 0; k < P_DIM; k++) {
            float4 b0 = *(const float4*)&Wa[k][4 * tC];
            float4 b1 = *(const float4*)&Wb[k][4 * tC];
            float a[8];
            #pragma unroll
            for (int i = 0; i < 8; i++) a[i] = xs[8 * tR + i][k];
            #pragma unroll
            for (int i = 0; i < 8; i++) {
                acc[i][0] = fmaf(a[i], b0.x, acc[i][0]);
                acc[i][1] = fmaf(a[i], b0.y, acc[i][1]);
                acc[i][2] = fmaf(a[i], b0.z, acc[i][2]);
                acc[i][3] = fmaf(a[i], b0.w, acc[i][3]);
                acc[i][4] = fmaf(a[i], b1.x, acc[i][4]);
                acc[i][5] = fmaf(a[i], b1.y, acc[i][5]);
                acc[i][6] = fmaf(a[i], b1.z, acc[i][6]);
                acc[i][7] = fmaf(a[i], b1.w, acc[i][7]);
            }
        }

        // BN + LIF epilogue; v round-trips through global scratch (bit-exact).
        #pragma unroll
        for (int i = 0; i < 8; i++) {
            const size_t vrow = (size_t)(row0 + 8 * tR + i) * D_DIM + 8 * tC;
            float v[8];
            if (t > 0) {
                float4 va = *(const float4*)&g_v[vrow];
                float4 vb = *(const float4*)&g_v[vrow + 4];
                v[0]=va.x; v[1]=va.y; v[2]=va.z; v[3]=va.w;
                v[4]=vb.x; v[5]=vb.y; v[6]=vb.z; v[7]=vb.w;
            } else {
                #pragma unroll
                for (int j = 0; j < 8; j++) v[j] = 0.f;
            }
            float sv[8];
            #pragma unroll
            for (int j = 0; j < 8; j++) {
                float4 prm = g_prm[8 * tC + j];     // (mean, rsq, gamma, beta)
                float h = (acc[i][j] - prm.x) * prm.y;
                h = h * prm.z + prm.w;
                float vv = v[j] + (h - v[j]) * 0.5f;              // v + (x-v)/tau
                float s = ((vv - 1.0f) >= 0.0f) ? 1.0f : 0.0f;    // H(v'-1)
                v[j] = vv * (1.0f - s);                           // hard reset
                sv[j] = s;
            }
            if (t < T_STEPS - 1) {
                *(float4*)&g_v[vrow]     = make_float4(v[0], v[1], v[2], v[3]);
                *(float4*)&g_v[vrow + 4] = make_float4(v[4], v[5], v[6], v[7]);
            }
            size_t o = ((size_t)t * BN_ROWS + row0 + 8 * tR + i) * D_DIM + 8 * tC;
            *(float4*)&out[o]     = make_float4(sv[0], sv[1], sv[2], sv[3]);
            *(float4*)&out[o + 4] = make_float4(sv[4], sv[5], sv[6], sv[7]);
        }
    }
}

// ---------------------------------------------------------------------------
extern "C" void kernel_launch(void* const* d_in, const int* in_sizes, int n_in,
                              void* d_out, int out_size) {
    const float* x     = (const float*)d_in[0];   // [4,64,1024,63]
    const float* W     = (const float*)d_in[1];   // [128,63]
    const float* gamma = (const float*)d_in[2];   // [128]
    const float* beta  = (const float*)d_in[3];   // [128]
    float* out = (float*)d_out;                   // [4,64,1024,128]

    zero_stats_kernel<<<16, 256>>>();
    stats_kernel<<<1024, 256>>>(x);
    finalize_kernel<<<D_DIM, 64>>>(W, gamma, beta);
    lif_main_kernel<<<BN_ROWS / 64, 128>>>(x, W, out);
}